// round 1
// baseline (speedup 1.0000x reference)
#include <cuda_runtime.h>
#include <cuda_bf16.h>
#include <math.h>

// Problem constants
#define Bq 8
#define Sq 1024
#define Dq 1024
#define DAq 256
#define Hq 16
#define HDq 64
#define Rq 32
#define Mtok (Bq*Sq)   // 8192

// ---------------- scratch (device globals; no allocation) ----------------
__device__ float g_pooled[Bq*Rq*Dq];        // [B,R,D]      1 MB
__device__ float g_root  [Bq*Rq*Dq];        // [B,R,D]      1 MB
__device__ float g_ksel  [Bq*Rq*DAq];       // [B,R,DA]
__device__ float g_qsel  [Mtok*DAq];        // [B,S,DA]     8 MB
__device__ unsigned char g_mask[Mtok*Rq];   // [B,S,R]
__device__ float g_q [Mtok*Dq];             // [B,H,S,64]   32 MB
__device__ float g_k [Mtok*Dq];             // [B,H,S,64]
__device__ float g_v [Mtok*Dq];             // [B,H,S,64]
__device__ float g_ctx[Mtok*Dq];            // [B,S,D]

// ---------------- warp reduce helpers ----------------
__device__ __forceinline__ float warp_max(float v) {
    #pragma unroll
    for (int o = 16; o; o >>= 1) v = fmaxf(v, __shfl_xor_sync(0xffffffffu, v, o));
    return v;
}
__device__ __forceinline__ float warp_sum(float v) {
    #pragma unroll
    for (int o = 16; o; o >>= 1) v += __shfl_xor_sync(0xffffffffu, v, o);
    return v;
}

// ---------------- 1) block mean-pool: pooled[b,r,:] = mean_{i<32} x[b, r*32+i, :] ----
__global__ void pool_kernel(const float* __restrict__ x, float* __restrict__ pooled) {
    int br = blockIdx.x;                 // 0..255  (b*32 + r)
    const float* base = x + (size_t)br * 32 * Dq;   // b*1024*D + r*32*D == br*32*D
    int d4 = threadIdx.x;                // 256 threads, float4 each
    float4 acc = make_float4(0.f, 0.f, 0.f, 0.f);
    #pragma unroll 4
    for (int i = 0; i < 32; i++) {
        float4 v = *(const float4*)(base + (size_t)i * Dq + d4 * 4);
        acc.x += v.x; acc.y += v.y; acc.z += v.z; acc.w += v.w;
    }
    const float s = 1.0f / 32.0f;
    acc.x *= s; acc.y *= s; acc.z *= s; acc.w *= s;
    *(float4*)(pooled + (size_t)br * Dq + d4 * 4) = acc;
}

// ---------------- 2) generic fp32 SGEMM 128x128x8, epilogue modes ----------------
// A[M,K] row-major, B[K,N] row-major, C[M,N]
// mode 0: plain store
// mode 1: q/k/v store: [M=B*S, N=H*64] -> [B,H,S,64]
// mode 2: C = acc + resid  (residual add, plain layout)
#define BM 128
#define BN 128
#define BKK 8
#define TM 8
#define TN 8
__global__ __launch_bounds__(256) void sgemm_kernel(
    const float* __restrict__ A, const float* __restrict__ B,
    float* __restrict__ C, int M, int N, int K,
    int mode, const float* __restrict__ resid)
{
    __shared__ float As[BKK][BM];
    __shared__ float Bs[BKK][BN];
    int tid = threadIdx.x;
    int bm = blockIdx.y * BM;
    int bn = blockIdx.x * BN;
    int tx = tid & 15, ty = tid >> 4;
    int tm0 = ty * TM, tn0 = tx * TN;

    float acc[TM][TN];
    #pragma unroll
    for (int i = 0; i < TM; i++)
        #pragma unroll
        for (int j = 0; j < TN; j++) acc[i][j] = 0.f;

    int arow = tid >> 1, acol = (tid & 1) * 4;   // A tile: 128 rows x 8 k, float4 along k
    int brow = tid >> 5, bcol = (tid & 31) * 4;  // B tile: 8 rows x 128 n, float4 along n

    const float* Ap = A + (size_t)(bm + arow) * K + acol;
    const float* Bp = B + (size_t)brow * N + bn + bcol;

    for (int k0 = 0; k0 < K; k0 += BKK) {
        float4 av = *(const float4*)(Ap + k0);
        As[acol + 0][arow] = av.x;
        As[acol + 1][arow] = av.y;
        As[acol + 2][arow] = av.z;
        As[acol + 3][arow] = av.w;
        float4 bv = *(const float4*)(Bp + (size_t)k0 * N);
        *(float4*)&Bs[brow][bcol] = bv;
        __syncthreads();
        #pragma unroll
        for (int k = 0; k < BKK; k++) {
            float ra[TM], rb[TN];
            *(float4*)&ra[0] = *(const float4*)&As[k][tm0];
            *(float4*)&ra[4] = *(const float4*)&As[k][tm0 + 4];
            *(float4*)&rb[0] = *(const float4*)&Bs[k][tn0];
            *(float4*)&rb[4] = *(const float4*)&Bs[k][tn0 + 4];
            #pragma unroll
            for (int i = 0; i < TM; i++)
                #pragma unroll
                for (int j = 0; j < TN; j++)
                    acc[i][j] += ra[i] * rb[j];
        }
        __syncthreads();
    }

    // epilogue
    if (mode == 0) {
        #pragma unroll
        for (int i = 0; i < TM; i++) {
            int m = bm + tm0 + i;
            #pragma unroll
            for (int j = 0; j < TN; j += 4) {
                float4 v = make_float4(acc[i][j], acc[i][j+1], acc[i][j+2], acc[i][j+3]);
                *(float4*)(C + (size_t)m * N + bn + tn0 + j) = v;
            }
        }
    } else if (mode == 1) {
        #pragma unroll
        for (int i = 0; i < TM; i++) {
            int m = bm + tm0 + i;
            int b = m >> 10, s = m & 1023;
            #pragma unroll
            for (int j = 0; j < TN; j++) {
                int n = bn + tn0 + j;
                int h = n >> 6, hd = n & 63;
                size_t dst = (((size_t)(b * Hq + h)) * Sq + s) * HDq + hd;
                C[dst] = acc[i][j];
            }
        }
    } else {
        #pragma unroll
        for (int i = 0; i < TM; i++) {
            int m = bm + tm0 + i;
            #pragma unroll
            for (int j = 0; j < TN; j += 4) {
                size_t off = (size_t)m * N + bn + tn0 + j;
                float4 r = *(const float4*)(resid + off);
                float4 v = make_float4(acc[i][j] + r.x, acc[i][j+1] + r.y,
                                       acc[i][j+2] + r.z, acc[i][j+3] + r.w);
                *(float4*)(C + off) = v;
            }
        }
    }
}

// ---------------- 3) block selection: softmax over R logits, threshold ----------------
// grid (B, S/8), block 256 (8 warps, one query per warp, lane = r)
__global__ __launch_bounds__(256) void select_kernel(
    const float* __restrict__ qsel, const float* __restrict__ ksel,
    unsigned char* __restrict__ mask)
{
    __shared__ float ks[Rq][DAq + 1];   // pad -> conflict free across r
    __shared__ float qrow[8][DAq];
    int b = blockIdx.x;
    int s0 = blockIdx.y * 8;
    int warp = threadIdx.x >> 5, lane = threadIdx.x & 31;
    int s = s0 + warp;

    const float* kp = ksel + (size_t)b * Rq * DAq;
    for (int i = threadIdx.x; i < Rq * DAq; i += 256)
        ks[i >> 8][i & 255] = kp[i];
    const float* qp = qsel + ((size_t)b * Sq + s) * DAq;
    for (int d = lane; d < DAq; d += 32) qrow[warp][d] = qp[d];
    __syncthreads();

    float logit = 0.f;
    #pragma unroll 8
    for (int d = 0; d < DAq; d++)
        logit += qrow[warp][d] * ks[lane][d];
    logit *= 0.0625f;                       // 1/sqrt(256)

    float mx = warp_max(logit);
    float e = expf(logit - mx);
    float sum = warp_sum(e);
    float prob = e / sum;
    bool own = (s >> 5) == lane;
    mask[((size_t)b * Sq + s) * Rq + lane] = (prob >= 0.5f || own) ? 1 : 0;
}

// ---------------- 4) block-sparse attention ----------------
// Q,K,V in [B,H,S,64]. grid (B*H, S/8), block 256 = 8 warps (one query/warp).
// Skips key blocks not needed by any of the 8 queries; online softmax per query.
__global__ __launch_bounds__(256) void attn_kernel(
    const float* __restrict__ Q, const float* __restrict__ K,
    const float* __restrict__ V, const unsigned char* __restrict__ mask,
    float* __restrict__ ctx)
{
    __shared__ float kt[32][65];
    __shared__ float vt[32][65];
    __shared__ float qs[8][65];
    __shared__ unsigned int needmask;

    int bh = blockIdx.x;               // b*16 + h
    int b = bh >> 4, h = bh & 15;
    int q0 = blockIdx.y * 8;
    int warp = threadIdx.x >> 5, lane = threadIdx.x & 31;
    int s = q0 + warp;

    const float* qptr = Q + ((size_t)bh * Sq + s) * HDq;
    qs[warp][lane] = qptr[lane];
    qs[warp][lane + 32] = qptr[lane + 32];

    const unsigned char* mrow = mask + ((size_t)b * Sq + s) * Rq;
    unsigned int mybits = __ballot_sync(0xffffffffu, mrow[lane] != 0);

    if (threadIdx.x == 0) needmask = 0;
    __syncthreads();
    if (lane == 0) atomicOr(&needmask, mybits);
    __syncthreads();
    unsigned int need = needmask;

    float mrun = -INFINITY, l = 0.f, c0 = 0.f, c1 = 0.f;
    const float* kbh = K + (size_t)bh * Sq * HDq;
    const float* vbh = V + (size_t)bh * Sq * HDq;

    for (int r = 0; r < 32; r++) {
        if (!((need >> r) & 1u)) continue;
        __syncthreads();   // protect kt/vt from previous iteration's readers
        // cooperative load of 32x64 K and V tiles (contiguous in global)
        const float* kb = kbh + (size_t)r * 32 * HDq;
        const float* vb = vbh + (size_t)r * 32 * HDq;
        for (int i = threadIdx.x; i < 512; i += 256) {
            int row = i >> 4, col = (i & 15) << 2;
            float4 f = *(const float4*)(kb + (i << 2));
            kt[row][col] = f.x; kt[row][col+1] = f.y; kt[row][col+2] = f.z; kt[row][col+3] = f.w;
            float4 g = *(const float4*)(vb + (i << 2));
            vt[row][col] = g.x; vt[row][col+1] = g.y; vt[row][col+2] = g.z; vt[row][col+3] = g.w;
        }
        __syncthreads();

        if ((mybits >> r) & 1u) {
            // lane computes score for key `lane` of this block
            float sc = 0.f;
            #pragma unroll 16
            for (int d = 0; d < HDq; d++)
                sc += qs[warp][d] * kt[lane][d];
            sc *= 0.125f;                    // 1/sqrt(64)
            float bmax = warp_max(sc);
            float mnew = fmaxf(mrun, bmax);
            float p = __expf(sc - mnew);
            float scale = __expf(mrun - mnew);   // exp(-inf)=0 on first block
            l = l * scale + warp_sum(p);
            c0 *= scale; c1 *= scale;
            #pragma unroll 8
            for (int j = 0; j < 32; j++) {
                float pj = __shfl_sync(0xffffffffu, p, j);
                c0 += pj * vt[j][lane];
                c1 += pj * vt[j][lane + 32];
            }
            mrun = mnew;
        }
    }

    float inv = 1.0f / l;   // own block always selected -> l > 0
    float* cp = ctx + ((size_t)(b * Sq + s)) * Dq + h * HDq;
    cp[lane] = c0 * inv;
    cp[lane + 32] = c1 * inv;
}

// ---------------- host launch ----------------
extern "C" void kernel_launch(void* const* d_in, const int* in_sizes, int n_in,
                              void* d_out, int out_size) {
    const float* x      = (const float*)d_in[0];
    const float* Wu     = (const float*)d_in[1];
    const float* Wk_sel = (const float*)d_in[2];
    const float* Wq_sel = (const float*)d_in[3];
    const float* Wq     = (const float*)d_in[4];
    const float* Wk     = (const float*)d_in[5];
    const float* Wv     = (const float*)d_in[6];
    const float* Wo     = (const float*)d_in[7];
    float* out = (float*)d_out;

    float *pooled, *root, *ksel, *qsel, *q, *k, *v, *ctx;
    unsigned char* mask;
    cudaGetSymbolAddress((void**)&pooled, g_pooled);
    cudaGetSymbolAddress((void**)&root,   g_root);
    cudaGetSymbolAddress((void**)&ksel,   g_ksel);
    cudaGetSymbolAddress((void**)&qsel,   g_qsel);
    cudaGetSymbolAddress((void**)&mask,   g_mask);
    cudaGetSymbolAddress((void**)&q,      g_q);
    cudaGetSymbolAddress((void**)&k,      g_k);
    cudaGetSymbolAddress((void**)&v,      g_v);
    cudaGetSymbolAddress((void**)&ctx,    g_ctx);

    // 1) block pooling
    pool_kernel<<<Bq * Rq, 256>>>(x, pooled);
    // 2) root_emb = pooled @ Wu        [256,1024,1024]
    sgemm_kernel<<<dim3(Dq / BN, (Bq * Rq) / BM), 256>>>(pooled, Wu, root, Bq * Rq, Dq, Dq, 0, nullptr);
    // 3) ksel = root @ Wk_sel          [256,256,1024]
    sgemm_kernel<<<dim3(DAq / BN, (Bq * Rq) / BM), 256>>>(root, Wk_sel, ksel, Bq * Rq, DAq, Dq, 0, nullptr);
    // 4) qsel = x @ Wq_sel             [8192,256,1024]
    sgemm_kernel<<<dim3(DAq / BN, Mtok / BM), 256>>>(x, Wq_sel, qsel, Mtok, DAq, Dq, 0, nullptr);
    // 5) selection mask
    select_kernel<<<dim3(Bq, Sq / 8), 256>>>(qsel, ksel, mask);
    // 6-8) q,k,v projections -> [B,H,S,64]
    sgemm_kernel<<<dim3(Dq / BN, Mtok / BM), 256>>>(x, Wq, q, Mtok, Dq, Dq, 1, nullptr);
    sgemm_kernel<<<dim3(Dq / BN, Mtok / BM), 256>>>(x, Wk, k, Mtok, Dq, Dq, 1, nullptr);
    sgemm_kernel<<<dim3(Dq / BN, Mtok / BM), 256>>>(x, Wv, v, Mtok, Dq, Dq, 1, nullptr);
    // 9) block-sparse attention
    attn_kernel<<<dim3(Bq * Hq, Sq / 8), 256>>>(q, k, v, mask, ctx);
    // 10) out = ctx @ Wo + x
    sgemm_kernel<<<dim3(Dq / BN, Mtok / BM), 256>>>(ctx, Wo, out, Mtok, Dq, Dq, 2, x);
}

// round 3
// speedup vs baseline: 3.1683x; 3.1683x over previous
#include <cuda_runtime.h>
#include <cuda_bf16.h>
#include <math.h>
#include <stdint.h>

// ---------------- problem constants ----------------
#define Bq 8
#define Sq 1024
#define Dq 1024
#define DAq 256
#define Hq 16
#define HDq 64
#define Rq 32
#define Mtok (Bq*Sq)   // 8192

// ---------------- scratch (device globals; no allocation) ----------------
__device__ float g_xr  [Mtok*Dq];           // rna-rounded x
__device__ float g_WuT [Dq*Dq];             // transposed+rounded weights [N,K]
__device__ float g_WqT [Dq*Dq];
__device__ float g_WkT [Dq*Dq];
__device__ float g_WvT [Dq*Dq];
__device__ float g_WoT [Dq*Dq];
__device__ float g_WqselT[DAq*Dq];
__device__ float g_WkselT[DAq*Dq];
__device__ float g_pooled[Bq*Rq*Dq];
__device__ float g_root  [Bq*Rq*Dq];
__device__ float g_ksel  [Bq*Rq*DAq];
__device__ float g_qsel  [Mtok*DAq];
__device__ unsigned char g_mask[Mtok*Rq];
__device__ float g_q [Mtok*Dq];             // [B,H,S,64]
__device__ float g_k [Mtok*Dq];
__device__ float g_v [Mtok*Dq];
__device__ float g_ctx[Mtok*Dq];            // [B,S,D] rounded

// ---------------- helpers ----------------
__device__ __forceinline__ float rna_tf32(float x) {
    uint32_t r; asm("cvt.rna.tf32.f32 %0, %1;" : "=r"(r) : "f"(x));
    return __uint_as_float(r);
}
__device__ __forceinline__ float warp_max(float v) {
    #pragma unroll
    for (int o = 16; o; o >>= 1) v = fmaxf(v, __shfl_xor_sync(0xffffffffu, v, o));
    return v;
}
__device__ __forceinline__ float warp_sum(float v) {
    #pragma unroll
    for (int o = 16; o; o >>= 1) v += __shfl_xor_sync(0xffffffffu, v, o);
    return v;
}
__device__ __forceinline__ uint32_t smem_u32(const void* p) {
    uint32_t a;
    asm("{ .reg .u64 t; cvta.to.shared.u64 t, %1; cvt.u32.u64 %0, t; }" : "=r"(a) : "l"(p));
    return a;
}

#define CP16(dst, src) \
    asm volatile("cp.async.cg.shared.global [%0], [%1], 16;" :: "r"(dst), "l"(src))
#define CPCOMMIT() asm volatile("cp.async.commit_group;")
#define CPWAIT(n)  asm volatile("cp.async.wait_group %0;" :: "n"(n))

__device__ __forceinline__ void mma_tf32(float c[4], const uint32_t a[4], const uint32_t b[2]) {
    asm volatile(
        "mma.sync.aligned.m16n8k8.row.col.f32.tf32.tf32.f32 "
        "{%0,%1,%2,%3}, {%4,%5,%6,%7}, {%8,%9}, {%0,%1,%2,%3};"
        : "+f"(c[0]), "+f"(c[1]), "+f"(c[2]), "+f"(c[3])
        : "r"(a[0]), "r"(a[1]), "r"(a[2]), "r"(a[3]), "r"(b[0]), "r"(b[1]));
}

// ---------------- prep kernels ----------------
__global__ void round_copy_kernel(const float4* __restrict__ in, float4* __restrict__ out, int n4) {
    int i = blockIdx.x * blockDim.x + threadIdx.x;
    if (i < n4) {
        float4 v = in[i];
        v.x = rna_tf32(v.x); v.y = rna_tf32(v.y); v.z = rna_tf32(v.z); v.w = rna_tf32(v.w);
        out[i] = v;
    }
}

// W[K,N] -> Wt[N,K] with tf32 rounding. grid(N/32, K/32), block(32,8)
__global__ void transpose_round_kernel(const float* __restrict__ W, float* __restrict__ Wt,
                                       int Kdim, int Ndim) {
    __shared__ float t[32][33];
    int n0 = blockIdx.x * 32, k0 = blockIdx.y * 32;
    int tx = threadIdx.x, ty = threadIdx.y;
    #pragma unroll
    for (int i = 0; i < 32; i += 8)
        t[ty + i][tx] = W[(size_t)(k0 + ty + i) * Ndim + n0 + tx];
    __syncthreads();
    #pragma unroll
    for (int i = 0; i < 32; i += 8)
        Wt[(size_t)(n0 + ty + i) * Kdim + k0 + tx] = rna_tf32(t[tx][ty + i]);
}

__global__ void pool_kernel(const float* __restrict__ x, float* __restrict__ pooled) {
    int br = blockIdx.x;
    const float* base = x + (size_t)br * 32 * Dq;
    int d4 = threadIdx.x;
    float4 acc = make_float4(0.f, 0.f, 0.f, 0.f);
    #pragma unroll 4
    for (int i = 0; i < 32; i++) {
        float4 v = *(const float4*)(base + (size_t)i * Dq + d4 * 4);
        acc.x += v.x; acc.y += v.y; acc.z += v.z; acc.w += v.w;
    }
    const float s = 1.0f / 32.0f;
    acc.x = rna_tf32(acc.x * s); acc.y = rna_tf32(acc.y * s);
    acc.z = rna_tf32(acc.z * s); acc.w = rna_tf32(acc.w * s);
    *(float4*)(pooled + (size_t)br * Dq + d4 * 4) = acc;
}

// ---------------- tf32 mma.sync GEMM ----------------
// C[M,N] = A[M,K] @ Bt[N,K]^T, inputs pre-rounded to tf32-exact fp32.
// modes: 0 plain, 1 qkv->[B,H,S,64], 2 +resid, 3 store rounded
#define GBM 128
#define GBN 128
#define GBK 32
#define LDT 36                       // smem row stride (floats): 32 + 4 pad
#define STG_FLOATS (GBM * LDT)       // 4608 floats per tile buffer
// smem: [A0][B0][A1][B1] = 4 * 4608 floats = 73728 B
#define SM_GEMM_BYTES (4 * STG_FLOATS * 4)

__global__ __launch_bounds__(256, 2)
void mma_gemm(const float* __restrict__ A, const float* __restrict__ Bt,
              float* __restrict__ C, int M, int N, int Kd,
              int mode, const float* __restrict__ resid)
{
    extern __shared__ float smf[];
    int tid = threadIdx.x;
    int wid = tid >> 5, lane = tid & 31;
    int warp_row = wid & 1;        // M dir: 2 warps, 64 rows each
    int warp_col = wid >> 1;       // N dir: 4 warps, 32 cols each
    int gr = lane >> 2;            // 0..7
    int gc = lane & 3;             // 0..3
    int bm = blockIdx.y * GBM;
    int bn = blockIdx.x * GBN;

    float c[4][4][4];
    #pragma unroll
    for (int f = 0; f < 4; f++)
        #pragma unroll
        for (int g = 0; g < 4; g++)
            #pragma unroll
            for (int i = 0; i < 4; i++) c[f][g][i] = 0.f;

    uint32_t sbase = smem_u32(smf);
    const int NK = Kd / GBK;

    // cp.async loader: 2048 cp16 per stage, 8 per thread (4 A + 4 B)
    auto load_stage = [&](int p, int k0) {
        float* Ab = smf + p * 2 * STG_FLOATS;
        float* Bb = Ab + STG_FLOATS;
        uint32_t Abase = sbase + (uint32_t)(p * 2 * STG_FLOATS) * 4;
        uint32_t Bbase = Abase + STG_FLOATS * 4;
        #pragma unroll
        for (int j = 0; j < 4; j++) {
            int idx = tid + j * 256;          // 0..1023
            int row = idx >> 3, kc = idx & 7;
            CP16(Abase + (uint32_t)(row * LDT + kc * 4) * 4,
                 A + (size_t)(bm + row) * Kd + k0 + kc * 4);
        }
        #pragma unroll
        for (int j = 0; j < 4; j++) {
            int idx = tid + j * 256;
            int row = idx >> 3, kc = idx & 7;
            CP16(Bbase + (uint32_t)(row * LDT + kc * 4) * 4,
                 Bt + (size_t)(bn + row) * Kd + k0 + kc * 4);
        }
        (void)Ab; (void)Bb;
    };

    load_stage(0, 0);
    CPCOMMIT();

    for (int ks = 0; ks < NK; ks++) {
        int p = ks & 1;
        if (ks + 1 < NK) {
            load_stage(p ^ 1, (ks + 1) * GBK);
            CPCOMMIT();
            CPWAIT(1);
        } else {
            CPWAIT(0);
        }
        __syncthreads();

        const float* As = smf + p * 2 * STG_FLOATS;
        const float* Bs = As + STG_FLOATS;

        #pragma unroll
        for (int kk = 0; kk < 4; kk++) {
            uint32_t a[4][4], b[4][2];
            #pragma unroll
            for (int f = 0; f < 4; f++) {
                const float* ap = As + (warp_row * 64 + f * 16 + gr) * LDT + kk * 8 + gc;
                a[f][0] = __float_as_uint(ap[0]);
                a[f][1] = __float_as_uint(ap[8 * LDT]);
                a[f][2] = __float_as_uint(ap[4]);
                a[f][3] = __float_as_uint(ap[8 * LDT + 4]);
            }
            #pragma unroll
            for (int g = 0; g < 4; g++) {
                const float* bp = Bs + (warp_col * 32 + g * 8 + gr) * LDT + kk * 8 + gc;
                b[g][0] = __float_as_uint(bp[0]);
                b[g][1] = __float_as_uint(bp[4]);
            }
            #pragma unroll
            for (int f = 0; f < 4; f++)
                #pragma unroll
                for (int g = 0; g < 4; g++)
                    mma_tf32(c[f][g], a[f], b[g]);
        }
        __syncthreads();
    }

    // ---- epilogue: stage 128x128 in smem (stride 132), coalesced store ----
    float* stg = smf;   // 128*132*4 = 67584 <= 73728
    #pragma unroll
    for (int f = 0; f < 4; f++) {
        #pragma unroll
        for (int g = 0; g < 4; g++) {
            int r0 = warp_row * 64 + f * 16 + gr;
            int c0 = warp_col * 32 + g * 8 + 2 * gc;
            stg[r0 * 132 + c0]           = c[f][g][0];
            stg[r0 * 132 + c0 + 1]       = c[f][g][1];
            stg[(r0 + 8) * 132 + c0]     = c[f][g][2];
            stg[(r0 + 8) * 132 + c0 + 1] = c[f][g][3];
        }
    }
    __syncthreads();

    int ccol = (tid & 31) * 4;
    #pragma unroll 4
    for (int rr = 0; rr < 16; rr++) {
        int r = (tid >> 5) + rr * 8;
        float4 v;
        v.x = stg[r * 132 + ccol + 0];
        v.y = stg[r * 132 + ccol + 1];
        v.z = stg[r * 132 + ccol + 2];
        v.w = stg[r * 132 + ccol + 3];
        int m = bm + r;
        int n = bn + ccol;
        if (mode == 0) {
            *(float4*)(C + (size_t)m * N + n) = v;
        } else if (mode == 1) {
            int b = m >> 10, s = m & 1023;
            int h = n >> 6, hd = n & 63;
            *(float4*)(C + (((size_t)(b * Hq + h)) * Sq + s) * HDq + hd) = v;
        } else if (mode == 2) {
            float4 rv = *(const float4*)(resid + (size_t)m * N + n);
            v.x += rv.x; v.y += rv.y; v.z += rv.z; v.w += rv.w;
            *(float4*)(C + (size_t)m * N + n) = v;
        } else {
            v.x = rna_tf32(v.x); v.y = rna_tf32(v.y);
            v.z = rna_tf32(v.z); v.w = rna_tf32(v.w);
            *(float4*)(C + (size_t)m * N + n) = v;
        }
    }
}

// ---------------- block selection ----------------
__global__ __launch_bounds__(256) void select_kernel(
    const float* __restrict__ qsel, const float* __restrict__ ksel,
    unsigned char* __restrict__ mask)
{
    __shared__ float ks[Rq][DAq + 1];
    __shared__ float qrow[8][DAq];
    int b = blockIdx.x;
    int s0 = blockIdx.y * 8;
    int warp = threadIdx.x >> 5, lane = threadIdx.x & 31;
    int s = s0 + warp;

    const float* kp = ksel + (size_t)b * Rq * DAq;
    for (int i = threadIdx.x; i < Rq * DAq; i += 256)
        ks[i >> 8][i & 255] = kp[i];
    const float* qp = qsel + ((size_t)b * Sq + s) * DAq;
    for (int d = lane; d < DAq; d += 32) qrow[warp][d] = qp[d];
    __syncthreads();

    float logit = 0.f;
    #pragma unroll 8
    for (int d = 0; d < DAq; d++)
        logit += qrow[warp][d] * ks[lane][d];
    logit *= 0.0625f;

    float mx = warp_max(logit);
    float e = expf(logit - mx);
    float sum = warp_sum(e);
    float prob = e / sum;
    bool own = (s >> 5) == lane;
    mask[((size_t)b * Sq + s) * Rq + lane] = (prob >= 0.5f || own) ? 1 : 0;
}

// ---------------- block-sparse attention ----------------
__global__ __launch_bounds__(256) void attn_kernel(
    const float* __restrict__ Q, const float* __restrict__ K,
    const float* __restrict__ V, const unsigned char* __restrict__ mask,
    float* __restrict__ ctx)
{
    __shared__ float kt[32][65];
    __shared__ float vt[32][65];
    __shared__ float qs[8][65];
    __shared__ unsigned int needmask;

    int bh = blockIdx.x;
    int b = bh >> 4, h = bh & 15;
    int q0 = blockIdx.y * 8;
    int warp = threadIdx.x >> 5, lane = threadIdx.x & 31;
    int s = q0 + warp;

    const float* qptr = Q + ((size_t)bh * Sq + s) * HDq;
    qs[warp][lane] = qptr[lane];
    qs[warp][lane + 32] = qptr[lane + 32];

    const unsigned char* mrow = mask + ((size_t)b * Sq + s) * Rq;
    unsigned int mybits = __ballot_sync(0xffffffffu, mrow[lane] != 0);

    if (threadIdx.x == 0) needmask = 0;
    __syncthreads();
    if (lane == 0) atomicOr(&needmask, mybits);
    __syncthreads();
    unsigned int need = needmask;

    float mrun = -INFINITY, l = 0.f, c0 = 0.f, c1 = 0.f;
    const float* kbh = K + (size_t)bh * Sq * HDq;
    const float* vbh = V + (size_t)bh * Sq * HDq;

    for (int r = 0; r < 32; r++) {
        if (!((need >> r) & 1u)) continue;
        __syncthreads();
        const float* kb = kbh + (size_t)r * 32 * HDq;
        const float* vb = vbh + (size_t)r * 32 * HDq;
        for (int i = threadIdx.x; i < 512; i += 256) {
            int row = i >> 4, col = (i & 15) << 2;
            float4 f = *(const float4*)(kb + (i << 2));
            kt[row][col] = f.x; kt[row][col+1] = f.y; kt[row][col+2] = f.z; kt[row][col+3] = f.w;
            float4 g = *(const float4*)(vb + (i << 2));
            vt[row][col] = g.x; vt[row][col+1] = g.y; vt[row][col+2] = g.z; vt[row][col+3] = g.w;
        }
        __syncthreads();

        if ((mybits >> r) & 1u) {
            float sc = 0.f;
            #pragma unroll 16
            for (int d = 0; d < HDq; d++)
                sc += qs[warp][d] * kt[lane][d];
            sc *= 0.125f;
            float bmax = warp_max(sc);
            float mnew = fmaxf(mrun, bmax);
            float p = __expf(sc - mnew);
            float scale = __expf(mrun - mnew);
            l = l * scale + warp_sum(p);
            c0 *= scale; c1 *= scale;
            #pragma unroll 8
            for (int j = 0; j < 32; j++) {
                float pj = __shfl_sync(0xffffffffu, p, j);
                c0 += pj * vt[j][lane];
                c1 += pj * vt[j][lane + 32];
            }
            mrun = mnew;
        }
    }

    float inv = 1.0f / l;
    float* cp = ctx + ((size_t)(b * Sq + s)) * Dq + h * HDq;
    cp[lane] = rna_tf32(c0 * inv);
    cp[lane + 32] = rna_tf32(c1 * inv);
}

// ---------------- host launch ----------------
extern "C" void kernel_launch(void* const* d_in, const int* in_sizes, int n_in,
                              void* d_out, int out_size) {
    const float* x      = (const float*)d_in[0];
    const float* Wu     = (const float*)d_in[1];
    const float* Wk_sel = (const float*)d_in[2];
    const float* Wq_sel = (const float*)d_in[3];
    const float* Wq     = (const float*)d_in[4];
    const float* Wk     = (const float*)d_in[5];
    const float* Wv     = (const float*)d_in[6];
    const float* Wo     = (const float*)d_in[7];
    float* out = (float*)d_out;

    float *xr, *WuT, *WqT, *WkT, *WvT, *WoT, *WqselT, *WkselT;
    float *pooled, *root, *ksel, *qsel, *q, *k, *v, *ctx;
    unsigned char* mask;
    cudaGetSymbolAddress((void**)&xr,     g_xr);
    cudaGetSymbolAddress((void**)&WuT,    g_WuT);
    cudaGetSymbolAddress((void**)&WqT,    g_WqT);
    cudaGetSymbolAddress((void**)&WkT,    g_WkT);
    cudaGetSymbolAddress((void**)&WvT,    g_WvT);
    cudaGetSymbolAddress((void**)&WoT,    g_WoT);
    cudaGetSymbolAddress((void**)&WqselT, g_WqselT);
    cudaGetSymbolAddress((void**)&WkselT, g_WkselT);
    cudaGetSymbolAddress((void**)&pooled, g_pooled);
    cudaGetSymbolAddress((void**)&root,   g_root);
    cudaGetSymbolAddress((void**)&ksel,   g_ksel);
    cudaGetSymbolAddress((void**)&qsel,   g_qsel);
    cudaGetSymbolAddress((void**)&mask,   g_mask);
    cudaGetSymbolAddress((void**)&q,      g_q);
    cudaGetSymbolAddress((void**)&k,      g_k);
    cudaGetSymbolAddress((void**)&v,      g_v);
    cudaGetSymbolAddress((void**)&ctx,    g_ctx);

    cudaFuncSetAttribute(mma_gemm, cudaFuncAttributeMaxDynamicSharedMemorySize, SM_GEMM_BYTES);

    // prep: round x, transpose+round weights
    round_copy_kernel<<<(Mtok * Dq / 4 + 255) / 256, 256>>>((const float4*)x, (float4*)xr, Mtok * Dq / 4);
    transpose_round_kernel<<<dim3(Dq / 32, Dq / 32), dim3(32, 8)>>>(Wu, WuT, Dq, Dq);
    transpose_round_kernel<<<dim3(Dq / 32, Dq / 32), dim3(32, 8)>>>(Wq, WqT, Dq, Dq);
    transpose_round_kernel<<<dim3(Dq / 32, Dq / 32), dim3(32, 8)>>>(Wk, WkT, Dq, Dq);
    transpose_round_kernel<<<dim3(Dq / 32, Dq / 32), dim3(32, 8)>>>(Wv, WvT, Dq, Dq);
    transpose_round_kernel<<<dim3(Dq / 32, Dq / 32), dim3(32, 8)>>>(Wo, WoT, Dq, Dq);
    transpose_round_kernel<<<dim3(DAq / 32, Dq / 32), dim3(32, 8)>>>(Wq_sel, WqselT, Dq, DAq);
    transpose_round_kernel<<<dim3(DAq / 32, Dq / 32), dim3(32, 8)>>>(Wk_sel, WkselT, Dq, DAq);

    pool_kernel<<<Bq * Rq, 256>>>(x, pooled);

    // root = pooled @ Wu (rounded store; feeds next GEMM)
    mma_gemm<<<dim3(Dq / GBN, (Bq * Rq) / GBM), 256, SM_GEMM_BYTES>>>(pooled, WuT, root, Bq * Rq, Dq, Dq, 3, nullptr);
    // ksel = root @ Wk_sel
    mma_gemm<<<dim3(DAq / GBN, (Bq * Rq) / GBM), 256, SM_GEMM_BYTES>>>(root, WkselT, ksel, Bq * Rq, DAq, Dq, 0, nullptr);
    // qsel = x @ Wq_sel
    mma_gemm<<<dim3(DAq / GBN, Mtok / GBM), 256, SM_GEMM_BYTES>>>(xr, WqselT, qsel, Mtok, DAq, Dq, 0, nullptr);
    // selection mask
    select_kernel<<<dim3(Bq, Sq / 8), 256>>>(qsel, ksel, mask);
    // q, k, v projections -> [B,H,S,64]
    mma_gemm<<<dim3(Dq / GBN, Mtok / GBM), 256, SM_GEMM_BYTES>>>(xr, WqT, q, Mtok, Dq, Dq, 1, nullptr);
    mma_gemm<<<dim3(Dq / GBN, Mtok / GBM), 256, SM_GEMM_BYTES>>>(xr, WkT, k, Mtok, Dq, Dq, 1, nullptr);
    mma_gemm<<<dim3(Dq / GBN, Mtok / GBM), 256, SM_GEMM_BYTES>>>(xr, WvT, v, Mtok, Dq, Dq, 1, nullptr);
    // attention (ctx rounded in epilogue)
    attn_kernel<<<dim3(Bq * Hq, Sq / 8), 256>>>(q, k, v, mask, ctx);
    // out = ctx @ Wo + x
    mma_gemm<<<dim3(Dq / GBN, Mtok / GBM), 256, SM_GEMM_BYTES>>>(ctx, WoT, out, Mtok, Dq, Dq, 2, x);
}

// round 5
// speedup vs baseline: 3.4543x; 1.0903x over previous
#include <cuda_runtime.h>
#include <cuda_bf16.h>
#include <math.h>
#include <stdint.h>

// ---------------- problem constants ----------------
#define Bq 8
#define Sq 1024
#define Dq 1024
#define DAq 256
#define Hq 16
#define HDq 64
#define Rq 32
#define Mtok (Bq*Sq)   // 8192
#define NCAT (DAq + 3*Dq)   // 3328 fused output cols

// ---------------- scratch (device globals; no allocation) ----------------
__device__ float g_xr  [Mtok*Dq];           // rna-rounded x
__device__ float g_WuT [Dq*Dq];
__device__ float g_WoT [Dq*Dq];
__device__ float g_WkselT[DAq*Dq];
__device__ float g_Wcat[NCAT*Dq];           // [qsel(256) | q(1024) | k | v] rows, K=1024
__device__ float g_pooled[Bq*Rq*Dq];
__device__ float g_root  [Bq*Rq*Dq];
__device__ float g_ksel  [Bq*Rq*DAq];
__device__ float g_qsel  [Mtok*DAq];
__device__ unsigned char g_mask[Mtok*Rq];
__device__ float g_q [Mtok*Dq];             // [B,H,S,64]
__device__ float g_k [Mtok*Dq];
__device__ float g_v [Mtok*Dq];
__device__ float g_ctx[Mtok*Dq];

// ---------------- helpers ----------------
__device__ __forceinline__ float rna_tf32(float x) {
    uint32_t r; asm("cvt.rna.tf32.f32 %0, %1;" : "=r"(r) : "f"(x));
    return __uint_as_float(r);
}
__device__ __forceinline__ float warp_max(float v) {
    #pragma unroll
    for (int o = 16; o; o >>= 1) v = fmaxf(v, __shfl_xor_sync(0xffffffffu, v, o));
    return v;
}
__device__ __forceinline__ float warp_sum(float v) {
    #pragma unroll
    for (int o = 16; o; o >>= 1) v += __shfl_xor_sync(0xffffffffu, v, o);
    return v;
}
__device__ __forceinline__ uint32_t smem_u32(const void* p) {
    uint32_t a;
    asm("{ .reg .u64 t; cvta.to.shared.u64 t, %1; cvt.u32.u64 %0, t; }" : "=r"(a) : "l"(p));
    return a;
}

#define CP16(dst, src) \
    asm volatile("cp.async.cg.shared.global [%0], [%1], 16;" :: "r"(dst), "l"(src))
#define CPCOMMIT() asm volatile("cp.async.commit_group;")
#define CPWAIT(n)  asm volatile("cp.async.wait_group %0;" :: "n"(n))

#define LDSM4(r0, r1, r2, r3, addr) \
    asm volatile("ldmatrix.sync.aligned.m8n8.x4.shared.b16 {%0,%1,%2,%3}, [%4];" \
        : "=r"(r0), "=r"(r1), "=r"(r2), "=r"(r3) : "r"(addr))

__device__ __forceinline__ void mma_tf32(float c[4], const uint32_t a[4], const uint32_t b[2]) {
    asm volatile(
        "mma.sync.aligned.m16n8k8.row.col.f32.tf32.tf32.f32 "
        "{%0,%1,%2,%3}, {%4,%5,%6,%7}, {%8,%9}, {%0,%1,%2,%3};"
        : "+f"(c[0]), "+f"(c[1]), "+f"(c[2]), "+f"(c[3])
        : "r"(a[0]), "r"(a[1]), "r"(a[2]), "r"(a[3]), "r"(b[0]), "r"(b[1]));
}

// ---------------- prep kernels ----------------
__global__ void round_copy_kernel(const float4* __restrict__ in, float4* __restrict__ out, int n4) {
    int i = blockIdx.x * blockDim.x + threadIdx.x;
    if (i < n4) {
        float4 v = in[i];
        v.x = rna_tf32(v.x); v.y = rna_tf32(v.y); v.z = rna_tf32(v.z); v.w = rna_tf32(v.w);
        out[i] = v;
    }
}

// W[K,N] -> Wt[N,K] with tf32 rounding. grid(N/32, K/32), block(32,8)
__global__ void transpose_round_kernel(const float* __restrict__ W, float* __restrict__ Wt,
                                       int Kdim, int Ndim) {
    __shared__ float t[32][33];
    int n0 = blockIdx.x * 32, k0 = blockIdx.y * 32;
    int tx = threadIdx.x, ty = threadIdx.y;
    #pragma unroll
    for (int i = 0; i < 32; i += 8)
        t[ty + i][tx] = W[(size_t)(k0 + ty + i) * Ndim + n0 + tx];
    __syncthreads();
    #pragma unroll
    for (int i = 0; i < 32; i += 8)
        Wt[(size_t)(n0 + ty + i) * Kdim + k0 + tx] = rna_tf32(t[tx][ty + i]);
}

__global__ void pool_kernel(const float* __restrict__ x, float* __restrict__ pooled) {
    int br = blockIdx.x;
    const float* base = x + (size_t)br * 32 * Dq;
    int d4 = threadIdx.x;
    float4 acc = make_float4(0.f, 0.f, 0.f, 0.f);
    #pragma unroll 4
    for (int i = 0; i < 32; i++) {
        float4 v = *(const float4*)(base + (size_t)i * Dq + d4 * 4);
        acc.x += v.x; acc.y += v.y; acc.z += v.z; acc.w += v.w;
    }
    const float s = 1.0f / 32.0f;
    acc.x = rna_tf32(acc.x * s); acc.y = rna_tf32(acc.y * s);
    acc.z = rna_tf32(acc.z * s); acc.w = rna_tf32(acc.w * s);
    *(float4*)(pooled + (size_t)br * Dq + d4 * 4) = acc;
}

// ---------------- tf32 mma.sync GEMM (ldmatrix fragments) ----------------
// C[M,N] = A[M,K] @ Bt[N,K]^T
// modes: 0 plain, 2 +resid, 3 store rounded, 4 fused routing (qsel/q/k/v)
#define GBM 128
#define GBN 128
#define GBK 32
#define LDT 36
#define STG_FLOATS (GBM * LDT)       // 4608
#define SM_GEMM_BYTES (4 * STG_FLOATS * 4)

__global__ __launch_bounds__(256, 2)
void mma_gemm(const float* __restrict__ A, const float* __restrict__ Bt,
              float* __restrict__ C, int M, int N, int Kd,
              int mode, const float* __restrict__ resid,
              float* __restrict__ pq, float* __restrict__ pk, float* __restrict__ pv)
{
    extern __shared__ float smf[];
    int tid = threadIdx.x;
    int wid = tid >> 5, lane = tid & 31;
    int warp_row = wid & 1;        // 2 warps along M (64 rows each)
    int warp_col = wid >> 1;       // 4 warps along N (32 cols each)
    int gr = lane >> 2, gc = lane & 3;
    int bm = blockIdx.y * GBM;
    int bn = blockIdx.x * GBN;

    // ldmatrix per-thread tile-row addressing
    int sel = lane >> 3, l8 = lane & 7;
    int a_row_off = (sel & 1) * 8 + l8;    // a0: r, a1: r+8, a2: r col+4, a3: r+8 col+4
    int a_col_off = (sel >> 1) * 4;
    int b_row_off = (sel >> 1) * 8 + l8;   // reg0/1: n-group g (k lo/hi), reg2/3: n-group g+1
    int b_col_off = (sel & 1) * 4;

    float c[4][4][4];
    #pragma unroll
    for (int f = 0; f < 4; f++)
        #pragma unroll
        for (int g = 0; g < 4; g++)
            #pragma unroll
            for (int i = 0; i < 4; i++) c[f][g][i] = 0.f;

    uint32_t sbase = smem_u32(smf);
    const int NK = Kd / GBK;

    auto load_stage = [&](int p, int k0) {
        uint32_t Abase = sbase + (uint32_t)(p * 2 * STG_FLOATS) * 4;
        uint32_t Bbase = Abase + STG_FLOATS * 4;
        #pragma unroll
        for (int j = 0; j < 4; j++) {
            int idx = tid + j * 256;
            int row = idx >> 3, kc = idx & 7;
            CP16(Abase + (uint32_t)(row * LDT + kc * 4) * 4,
                 A + (size_t)(bm + row) * Kd + k0 + kc * 4);
        }
        #pragma unroll
        for (int j = 0; j < 4; j++) {
            int idx = tid + j * 256;
            int row = idx >> 3, kc = idx & 7;
            CP16(Bbase + (uint32_t)(row * LDT + kc * 4) * 4,
                 Bt + (size_t)(bn + row) * Kd + k0 + kc * 4);
        }
    };

    load_stage(0, 0);
    CPCOMMIT();

    for (int ks = 0; ks < NK; ks++) {
        int p = ks & 1;
        if (ks + 1 < NK) {
            load_stage(p ^ 1, (ks + 1) * GBK);
            CPCOMMIT();
            CPWAIT(1);
        } else {
            CPWAIT(0);
        }
        __syncthreads();

        uint32_t As = sbase + (uint32_t)(p * 2 * STG_FLOATS) * 4;
        uint32_t Bs = As + STG_FLOATS * 4;
        uint32_t aAddr = As + (uint32_t)((warp_row * 64 + a_row_off) * LDT + a_col_off) * 4;
        uint32_t bAddr = Bs + (uint32_t)((warp_col * 32 + b_row_off) * LDT + b_col_off) * 4;

        #pragma unroll
        for (int kk = 0; kk < 4; kk++) {
            uint32_t a[4][4], b[4][2];
            #pragma unroll
            for (int f = 0; f < 4; f++)
                LDSM4(a[f][0], a[f][1], a[f][2], a[f][3],
                      aAddr + (uint32_t)(f * 16 * LDT + kk * 8) * 4);
            #pragma unroll
            for (int gp = 0; gp < 2; gp++)
                LDSM4(b[2*gp][0], b[2*gp][1], b[2*gp+1][0], b[2*gp+1][1],
                      bAddr + (uint32_t)(gp * 16 * LDT + kk * 8) * 4);
            #pragma unroll
            for (int f = 0; f < 4; f++)
                #pragma unroll
                for (int g = 0; g < 4; g++)
                    mma_tf32(c[f][g], a[f], b[g]);
        }
        __syncthreads();
    }

    // ---- epilogue: stage 128x128 in smem, coalesced routing stores ----
    float* stg = smf;   // 128*132 floats = 67584 B <= 73728
    #pragma unroll
    for (int f = 0; f < 4; f++) {
        #pragma unroll
        for (int g = 0; g < 4; g++) {
            int r0 = warp_row * 64 + f * 16 + gr;
            int c0 = warp_col * 32 + g * 8 + 2 * gc;
            stg[r0 * 132 + c0]           = c[f][g][0];
            stg[r0 * 132 + c0 + 1]       = c[f][g][1];
            stg[(r0 + 8) * 132 + c0]     = c[f][g][2];
            stg[(r0 + 8) * 132 + c0 + 1] = c[f][g][3];
        }
    }
    __syncthreads();

    int ccol = (tid & 31) * 4;
    #pragma unroll 4
    for (int rr = 0; rr < 16; rr++) {
        int r = (tid >> 5) + rr * 8;
        float4 v;
        v.x = stg[r * 132 + ccol + 0];
        v.y = stg[r * 132 + ccol + 1];
        v.z = stg[r * 132 + ccol + 2];
        v.w = stg[r * 132 + ccol + 3];
        int m = bm + r;
        int n = bn + ccol;
        if (mode == 0) {
            *(float4*)(C + (size_t)m * N + n) = v;
        } else if (mode == 2) {
            float4 rv = *(const float4*)(resid + (size_t)m * N + n);
            v.x += rv.x; v.y += rv.y; v.z += rv.z; v.w += rv.w;
            *(float4*)(C + (size_t)m * N + n) = v;
        } else if (mode == 3) {
            v.x = rna_tf32(v.x); v.y = rna_tf32(v.y);
            v.z = rna_tf32(v.z); v.w = rna_tf32(v.w);
            *(float4*)(C + (size_t)m * N + n) = v;
        } else {
            // fused routing: cols [0,256) -> qsel, then q,k,v in [B,H,S,64]
            if (n < DAq) {
                *(float4*)(C + (size_t)m * DAq + n) = v;
            } else {
                int n2 = n - DAq;
                int proj = n2 >> 10, nn = n2 & 1023;
                int h = nn >> 6, hd = nn & 63;
                int b = m >> 10, s = m & 1023;
                float* P = (proj == 0) ? pq : (proj == 1) ? pk : pv;
                *(float4*)(P + (((size_t)(b * Hq + h)) * Sq + s) * HDq + hd) = v;
            }
        }
    }
}

// ---------------- block selection ----------------
__global__ __launch_bounds__(256) void select_kernel(
    const float* __restrict__ qsel, const float* __restrict__ ksel,
    unsigned char* __restrict__ mask)
{
    __shared__ float ks[Rq][DAq + 1];
    __shared__ float qrow[8][DAq];
    int b = blockIdx.x;
    int s0 = blockIdx.y * 8;
    int warp = threadIdx.x >> 5, lane = threadIdx.x & 31;
    int s = s0 + warp;

    const float* kp = ksel + (size_t)b * Rq * DAq;
    for (int i = threadIdx.x; i < Rq * DAq; i += 256)
        ks[i >> 8][i & 255] = kp[i];
    const float* qp = qsel + ((size_t)b * Sq + s) * DAq;
    for (int d = lane; d < DAq; d += 32) qrow[warp][d] = qp[d];
    __syncthreads();

    float logit = 0.f;
    #pragma unroll 8
    for (int d = 0; d < DAq; d++)
        logit += qrow[warp][d] * ks[lane][d];
    logit *= 0.0625f;

    float mx = warp_max(logit);
    float e = expf(logit - mx);
    float sum = warp_sum(e);
    float prob = e / sum;
    bool own = (s >> 5) == lane;
    mask[((size_t)b * Sq + s) * Rq + lane] = (prob >= 0.5f || own) ? 1 : 0;
}

// ---------------- block-sparse attention ----------------
__global__ __launch_bounds__(256) void attn_kernel(
    const float* __restrict__ Q, const float* __restrict__ K,
    const float* __restrict__ V, const unsigned char* __restrict__ mask,
    float* __restrict__ ctx)
{
    __shared__ float kt[32][65];
    __shared__ float vt[32][65];
    __shared__ float qs[8][65];
    __shared__ unsigned int needmask;

    int bh = blockIdx.x;
    int b = bh >> 4, h = bh & 15;
    int q0 = blockIdx.y * 8;
    int warp = threadIdx.x >> 5, lane = threadIdx.x & 31;
    int s = q0 + warp;

    const float* qptr = Q + ((size_t)bh * Sq + s) * HDq;
    qs[warp][lane] = qptr[lane];
    qs[warp][lane + 32] = qptr[lane + 32];

    const unsigned char* mrow = mask + ((size_t)b * Sq + s) * Rq;
    unsigned int mybits = __ballot_sync(0xffffffffu, mrow[lane] != 0);

    if (threadIdx.x == 0) needmask = 0;
    __syncthreads();
    if (lane == 0) atomicOr(&needmask, mybits);
    __syncthreads();
    unsigned int need = needmask;

    float mrun = -INFINITY, l = 0.f, c0 = 0.f, c1 = 0.f;
    const float* kbh = K + (size_t)bh * Sq * HDq;
    const float* vbh = V + (size_t)bh * Sq * HDq;

    for (int r = 0; r < 32; r++) {
        if (!((need >> r) & 1u)) continue;
        __syncthreads();
        const float* kb = kbh + (size_t)r * 32 * HDq;
        const float* vb = vbh + (size_t)r * 32 * HDq;
        for (int i = threadIdx.x; i < 512; i += 256) {
            int row = i >> 4, col = (i & 15) << 2;
            float4 f = *(const float4*)(kb + (i << 2));
            kt[row][col] = f.x; kt[row][col+1] = f.y; kt[row][col+2] = f.z; kt[row][col+3] = f.w;
            float4 g = *(const float4*)(vb + (i << 2));
            vt[row][col] = g.x; vt[row][col+1] = g.y; vt[row][col+2] = g.z; vt[row][col+3] = g.w;
        }
        __syncthreads();

        if ((mybits >> r) & 1u) {
            float sc = 0.f;
            #pragma unroll 16
            for (int d = 0; d < HDq; d++)
                sc += qs[warp][d] * kt[lane][d];
            sc *= 0.125f;
            float bmax = warp_max(sc);
            float mnew = fmaxf(mrun, bmax);
            float p = __expf(sc - mnew);
            float scale = __expf(mrun - mnew);
            l = l * scale + warp_sum(p);
            c0 *= scale; c1 *= scale;
            #pragma unroll 8
            for (int j = 0; j < 32; j++) {
                float pj = __shfl_sync(0xffffffffu, p, j);
                c0 += pj * vt[j][lane];
                c1 += pj * vt[j][lane + 32];
            }
            mrun = mnew;
        }
    }

    float inv = 1.0f / l;
    float* cp = ctx + ((size_t)(b * Sq + s)) * Dq + h * HDq;
    cp[lane] = rna_tf32(c0 * inv);
    cp[lane + 32] = rna_tf32(c1 * inv);
}

// ---------------- host launch ----------------
extern "C" void kernel_launch(void* const* d_in, const int* in_sizes, int n_in,
                              void* d_out, int out_size) {
    const float* x      = (const float*)d_in[0];
    const float* Wu     = (const float*)d_in[1];
    const float* Wk_sel = (const float*)d_in[2];
    const float* Wq_sel = (const float*)d_in[3];
    const float* Wq     = (const float*)d_in[4];
    const float* Wk     = (const float*)d_in[5];
    const float* Wv     = (const float*)d_in[6];
    const float* Wo     = (const float*)d_in[7];
    float* out = (float*)d_out;

    float *xr, *WuT, *WoT, *WkselT, *Wcat;
    float *pooled, *root, *ksel, *qsel, *q, *k, *v, *ctx;
    unsigned char* mask;
    cudaGetSymbolAddress((void**)&xr,     g_xr);
    cudaGetSymbolAddress((void**)&WuT,    g_WuT);
    cudaGetSymbolAddress((void**)&WoT,    g_WoT);
    cudaGetSymbolAddress((void**)&WkselT, g_WkselT);
    cudaGetSymbolAddress((void**)&Wcat,   g_Wcat);
    cudaGetSymbolAddress((void**)&pooled, g_pooled);
    cudaGetSymbolAddress((void**)&root,   g_root);
    cudaGetSymbolAddress((void**)&ksel,   g_ksel);
    cudaGetSymbolAddress((void**)&qsel,   g_qsel);
    cudaGetSymbolAddress((void**)&mask,   g_mask);
    cudaGetSymbolAddress((void**)&q,      g_q);
    cudaGetSymbolAddress((void**)&k,      g_k);
    cudaGetSymbolAddress((void**)&v,      g_v);
    cudaGetSymbolAddress((void**)&ctx,    g_ctx);

    cudaFuncSetAttribute(mma_gemm, cudaFuncAttributeMaxDynamicSharedMemorySize, SM_GEMM_BYTES);

    // prep: round x; transpose+round weights (qsel/q/k/v into concatenated buffer)
    round_copy_kernel<<<(Mtok * Dq / 4 + 255) / 256, 256>>>((const float4*)x, (float4*)xr, Mtok * Dq / 4);
    transpose_round_kernel<<<dim3(Dq / 32, Dq / 32), dim3(32, 8)>>>(Wu, WuT, Dq, Dq);
    transpose_round_kernel<<<dim3(Dq / 32, Dq / 32), dim3(32, 8)>>>(Wo, WoT, Dq, Dq);
    transpose_round_kernel<<<dim3(DAq / 32, Dq / 32), dim3(32, 8)>>>(Wk_sel, WkselT, Dq, DAq);
    transpose_round_kernel<<<dim3(DAq / 32, Dq / 32), dim3(32, 8)>>>(Wq_sel, Wcat, Dq, DAq);
    transpose_round_kernel<<<dim3(Dq / 32, Dq / 32), dim3(32, 8)>>>(Wq, Wcat + (size_t)DAq * Dq, Dq, Dq);
    transpose_round_kernel<<<dim3(Dq / 32, Dq / 32), dim3(32, 8)>>>(Wk, Wcat + (size_t)(DAq + Dq) * Dq, Dq, Dq);
    transpose_round_kernel<<<dim3(Dq / 32, Dq / 32), dim3(32, 8)>>>(Wv, Wcat + (size_t)(DAq + 2 * Dq) * Dq, Dq, Dq);

    pool_kernel<<<Bq * Rq, 256>>>(x, pooled);

    // root = pooled @ Wu (rounded; feeds next GEMM)
    mma_gemm<<<dim3(Dq / GBN, (Bq * Rq) / GBM), 256, SM_GEMM_BYTES>>>(
        pooled, WuT, root, Bq * Rq, Dq, Dq, 3, nullptr, nullptr, nullptr, nullptr);
    // ksel = root @ Wk_sel
    mma_gemm<<<dim3(DAq / GBN, (Bq * Rq) / GBM), 256, SM_GEMM_BYTES>>>(
        root, WkselT, ksel, Bq * Rq, DAq, Dq, 0, nullptr, nullptr, nullptr, nullptr);
    // fused: [qsel | q | k | v] = xr @ Wcat^T
    mma_gemm<<<dim3(NCAT / GBN, Mtok / GBM), 256, SM_GEMM_BYTES>>>(
        xr, Wcat, qsel, Mtok, NCAT, Dq, 4, nullptr, q, k, v);
    // selection mask
    select_kernel<<<dim3(Bq, Sq / 8), 256>>>(qsel, ksel, mask);
    // attention
    attn_kernel<<<dim3(Bq * Hq, Sq / 8), 256>>>(q, k, v, mask, ctx);
    // out = ctx @ Wo + x
    mma_gemm<<<dim3(Dq / GBN, Mtok / GBM), 256, SM_GEMM_BYTES>>>(
        ctx, WoT, out, Mtok, Dq, Dq, 2, x, nullptr, nullptr, nullptr);
}

// round 6
// speedup vs baseline: 3.6211x; 1.0483x over previous
#include <cuda_runtime.h>
#include <cuda_bf16.h>
#include <math.h>
#include <stdint.h>

// ---------------- problem constants ----------------
#define Bq 8
#define Sq 1024
#define Dq 1024
#define DAq 256
#define Hq 16
#define HDq 64
#define Rq 32
#define Mtok (Bq*Sq)   // 8192
#define NCAT (DAq + 3*Dq)   // 3328 fused output cols

// ---------------- scratch (device globals; no allocation) ----------------
__device__ float g_xr  [Mtok*Dq];           // rna-rounded x
__device__ float g_WuT [Dq*Dq];
__device__ float g_WoT [Dq*Dq];
__device__ float g_WkselT[DAq*Dq];
__device__ float g_Wcat[NCAT*Dq];           // [qsel(256) | q | k | v] rows, K=1024
__device__ float g_pooled[Bq*Rq*Dq];
__device__ float g_root  [Bq*Rq*Dq];
__device__ float g_ksel  [Bq*Rq*DAq];
__device__ float g_qsel  [Mtok*DAq];
__device__ unsigned char g_mask[Mtok*Rq];
__device__ float g_q [Mtok*Dq];             // [B,H,S,64]
__device__ float g_k [Mtok*Dq];
__device__ float g_v [Mtok*Dq];
__device__ float g_ctx[Mtok*Dq];

// ---------------- helpers ----------------
__device__ __forceinline__ float rna_tf32(float x) {
    uint32_t r; asm("cvt.rna.tf32.f32 %0, %1;" : "=r"(r) : "f"(x));
    return __uint_as_float(r);
}
__device__ __forceinline__ float warp_max(float v) {
    #pragma unroll
    for (int o = 16; o; o >>= 1) v = fmaxf(v, __shfl_xor_sync(0xffffffffu, v, o));
    return v;
}
__device__ __forceinline__ float warp_sum(float v) {
    #pragma unroll
    for (int o = 16; o; o >>= 1) v += __shfl_xor_sync(0xffffffffu, v, o);
    return v;
}
__device__ __forceinline__ uint32_t smem_u32(const void* p) {
    uint32_t a;
    asm("{ .reg .u64 t; cvta.to.shared.u64 t, %1; cvt.u32.u64 %0, t; }" : "=r"(a) : "l"(p));
    return a;
}

#define CP16(dst, src) \
    asm volatile("cp.async.cg.shared.global [%0], [%1], 16;" :: "r"(dst), "l"(src))
#define CPCOMMIT() asm volatile("cp.async.commit_group;")
#define CPWAIT(n)  asm volatile("cp.async.wait_group %0;" :: "n"(n))

#define LDSM4(r0, r1, r2, r3, addr) \
    asm volatile("ldmatrix.sync.aligned.m8n8.x4.shared.b16 {%0,%1,%2,%3}, [%4];" \
        : "=r"(r0), "=r"(r1), "=r"(r2), "=r"(r3) : "r"(addr))

__device__ __forceinline__ void mma_tf32(float c[4], const uint32_t a[4], const uint32_t b[2]) {
    asm volatile(
        "mma.sync.aligned.m16n8k8.row.col.f32.tf32.tf32.f32 "
        "{%0,%1,%2,%3}, {%4,%5,%6,%7}, {%8,%9}, {%0,%1,%2,%3};"
        : "+f"(c[0]), "+f"(c[1]), "+f"(c[2]), "+f"(c[3])
        : "r"(a[0]), "r"(a[1]), "r"(a[2]), "r"(a[3]), "r"(b[0]), "r"(b[1]));
}

// ---------------- prep kernels ----------------
__global__ void round_copy_kernel(const float4* __restrict__ in, float4* __restrict__ out, int n4) {
    int i = blockIdx.x * blockDim.x + threadIdx.x;
    if (i < n4) {
        float4 v = in[i];
        v.x = rna_tf32(v.x); v.y = rna_tf32(v.y); v.z = rna_tf32(v.z); v.w = rna_tf32(v.w);
        out[i] = v;
    }
}

// W[K,N] -> Wt[N,K] with tf32 rounding. grid(N/32, K/32), block(32,8)
__global__ void transpose_round_kernel(const float* __restrict__ W, float* __restrict__ Wt,
                                       int Kdim, int Ndim) {
    __shared__ float t[32][33];
    int n0 = blockIdx.x * 32, k0 = blockIdx.y * 32;
    int tx = threadIdx.x, ty = threadIdx.y;
    #pragma unroll
    for (int i = 0; i < 32; i += 8)
        t[ty + i][tx] = W[(size_t)(k0 + ty + i) * Ndim + n0 + tx];
    __syncthreads();
    #pragma unroll
    for (int i = 0; i < 32; i += 8)
        Wt[(size_t)(n0 + ty + i) * Kdim + k0 + tx] = rna_tf32(t[tx][ty + i]);
}

__global__ void pool_kernel(const float* __restrict__ x, float* __restrict__ pooled) {
    int br = blockIdx.x;
    const float* base = x + (size_t)br * 32 * Dq;
    int d4 = threadIdx.x;
    float4 acc = make_float4(0.f, 0.f, 0.f, 0.f);
    #pragma unroll 4
    for (int i = 0; i < 32; i++) {
        float4 v = *(const float4*)(base + (size_t)i * Dq + d4 * 4);
        acc.x += v.x; acc.y += v.y; acc.z += v.z; acc.w += v.w;
    }
    const float s = 1.0f / 32.0f;
    acc.x = rna_tf32(acc.x * s); acc.y = rna_tf32(acc.y * s);
    acc.z = rna_tf32(acc.z * s); acc.w = rna_tf32(acc.w * s);
    *(float4*)(pooled + (size_t)br * Dq + d4 * 4) = acc;
}

// ---------------- tf32 mma.sync GEMM (ldmatrix fragments) ----------------
// C[M,N] = A[M,K] @ Bt[N,K]^T
// modes: 0 plain, 2 +resid, 3 store rounded, 4 fused routing (qsel/q/k/v)
#define GBM 128
#define GBN 128
#define GBK 32
#define LDT 36
#define STG_FLOATS (GBM * LDT)       // 4608
#define SM_GEMM_BYTES (4 * STG_FLOATS * 4)

__global__ __launch_bounds__(256, 2)
void mma_gemm(const float* __restrict__ A, const float* __restrict__ Bt,
              float* __restrict__ C, int M, int N, int Kd,
              int mode, const float* __restrict__ resid,
              float* __restrict__ pq, float* __restrict__ pk, float* __restrict__ pv)
{
    extern __shared__ float smf[];
    int tid = threadIdx.x;
    int wid = tid >> 5, lane = tid & 31;
    int warp_row = wid & 1;        // 2 warps along M (64 rows each)
    int warp_col = wid >> 1;       // 4 warps along N (32 cols each)
    int gr = lane >> 2, gc = lane & 3;
    int bm = blockIdx.y * GBM;
    int bn = blockIdx.x * GBN;

    // ldmatrix per-thread tile-row addressing
    int sel = lane >> 3, l8 = lane & 7;
    int a_row_off = (sel & 1) * 8 + l8;
    int a_col_off = (sel >> 1) * 4;
    int b_row_off = (sel >> 1) * 8 + l8;
    int b_col_off = (sel & 1) * 4;

    float c[4][4][4];
    #pragma unroll
    for (int f = 0; f < 4; f++)
        #pragma unroll
        for (int g = 0; g < 4; g++)
            #pragma unroll
            for (int i = 0; i < 4; i++) c[f][g][i] = 0.f;

    uint32_t sbase = smem_u32(smf);
    const int NK = Kd / GBK;

    auto load_stage = [&](int p, int k0) {
        uint32_t Abase = sbase + (uint32_t)(p * 2 * STG_FLOATS) * 4;
        uint32_t Bbase = Abase + STG_FLOATS * 4;
        #pragma unroll
        for (int j = 0; j < 4; j++) {
            int idx = tid + j * 256;
            int row = idx >> 3, kc = idx & 7;
            CP16(Abase + (uint32_t)(row * LDT + kc * 4) * 4,
                 A + (size_t)(bm + row) * Kd + k0 + kc * 4);
        }
        #pragma unroll
        for (int j = 0; j < 4; j++) {
            int idx = tid + j * 256;
            int row = idx >> 3, kc = idx & 7;
            CP16(Bbase + (uint32_t)(row * LDT + kc * 4) * 4,
                 Bt + (size_t)(bn + row) * Kd + k0 + kc * 4);
        }
    };

    load_stage(0, 0);
    CPCOMMIT();

    for (int ks = 0; ks < NK; ks++) {
        int p = ks & 1;
        if (ks + 1 < NK) {
            load_stage(p ^ 1, (ks + 1) * GBK);
            CPCOMMIT();
            CPWAIT(1);
        } else {
            CPWAIT(0);
        }
        __syncthreads();

        uint32_t As = sbase + (uint32_t)(p * 2 * STG_FLOATS) * 4;
        uint32_t Bs = As + STG_FLOATS * 4;
        uint32_t aAddr = As + (uint32_t)((warp_row * 64 + a_row_off) * LDT + a_col_off) * 4;
        uint32_t bAddr = Bs + (uint32_t)((warp_col * 32 + b_row_off) * LDT + b_col_off) * 4;

        #pragma unroll
        for (int kk = 0; kk < 4; kk++) {
            uint32_t a[4][4], b[4][2];
            #pragma unroll
            for (int f = 0; f < 4; f++)
                LDSM4(a[f][0], a[f][1], a[f][2], a[f][3],
                      aAddr + (uint32_t)(f * 16 * LDT + kk * 8) * 4);
            #pragma unroll
            for (int gp = 0; gp < 2; gp++)
                LDSM4(b[2*gp][0], b[2*gp][1], b[2*gp+1][0], b[2*gp+1][1],
                      bAddr + (uint32_t)(gp * 16 * LDT + kk * 8) * 4);
            #pragma unroll
            for (int f = 0; f < 4; f++)
                #pragma unroll
                for (int g = 0; g < 4; g++)
                    mma_tf32(c[f][g], a[f], b[g]);
        }
        __syncthreads();
    }

    // ---- epilogue: stage 128x128 in smem, coalesced routing stores ----
    float* stg = smf;
    #pragma unroll
    for (int f = 0; f < 4; f++) {
        #pragma unroll
        for (int g = 0; g < 4; g++) {
            int r0 = warp_row * 64 + f * 16 + gr;
            int c0 = warp_col * 32 + g * 8 + 2 * gc;
            stg[r0 * 132 + c0]           = c[f][g][0];
            stg[r0 * 132 + c0 + 1]       = c[f][g][1];
            stg[(r0 + 8) * 132 + c0]     = c[f][g][2];
            stg[(r0 + 8) * 132 + c0 + 1] = c[f][g][3];
        }
    }
    __syncthreads();

    int ccol = (tid & 31) * 4;
    #pragma unroll 4
    for (int rr = 0; rr < 16; rr++) {
        int r = (tid >> 5) + rr * 8;
        float4 v;
        v.x = stg[r * 132 + ccol + 0];
        v.y = stg[r * 132 + ccol + 1];
        v.z = stg[r * 132 + ccol + 2];
        v.w = stg[r * 132 + ccol + 3];
        int m = bm + r;
        int n = bn + ccol;
        if (mode == 0) {
            *(float4*)(C + (size_t)m * N + n) = v;
        } else if (mode == 2) {
            float4 rv = *(const float4*)(resid + (size_t)m * N + n);
            v.x += rv.x; v.y += rv.y; v.z += rv.z; v.w += rv.w;
            *(float4*)(C + (size_t)m * N + n) = v;
        } else if (mode == 3) {
            v.x = rna_tf32(v.x); v.y = rna_tf32(v.y);
            v.z = rna_tf32(v.z); v.w = rna_tf32(v.w);
            *(float4*)(C + (size_t)m * N + n) = v;
        } else {
            if (n < DAq) {
                *(float4*)(C + (size_t)m * DAq + n) = v;
            } else {
                int n2 = n - DAq;
                int proj = n2 >> 10, nn = n2 & 1023;
                int h = nn >> 6, hd = nn & 63;
                int b = m >> 10, s = m & 1023;
                float* P = (proj == 0) ? pq : (proj == 1) ? pk : pv;
                *(float4*)(P + (((size_t)(b * Hq + h)) * Sq + s) * HDq + hd) = v;
            }
        }
    }
}

// ---------------- block selection ----------------
__global__ __launch_bounds__(256) void select_kernel(
    const float* __restrict__ qsel, const float* __restrict__ ksel,
    unsigned char* __restrict__ mask)
{
    __shared__ float ks[Rq][DAq + 1];
    __shared__ float qrow[8][DAq];
    int b = blockIdx.x;
    int s0 = blockIdx.y * 8;
    int warp = threadIdx.x >> 5, lane = threadIdx.x & 31;
    int s = s0 + warp;

    const float* kp = ksel + (size_t)b * Rq * DAq;
    for (int i = threadIdx.x; i < Rq * DAq; i += 256)
        ks[i >> 8][i & 255] = kp[i];
    const float* qp = qsel + ((size_t)b * Sq + s) * DAq;
    for (int d = lane; d < DAq; d += 32) qrow[warp][d] = qp[d];
    __syncthreads();

    float logit = 0.f;
    #pragma unroll 8
    for (int d = 0; d < DAq; d++)
        logit += qrow[warp][d] * ks[lane][d];
    logit *= 0.0625f;

    float mx = warp_max(logit);
    float e = expf(logit - mx);
    float sum = warp_sum(e);
    float prob = e / sum;
    bool own = (s >> 5) == lane;
    mask[((size_t)b * Sq + s) * Rq + lane] = (prob >= 0.5f || own) ? 1 : 0;
}

// ---------------- block-sparse attention (32 queries per CTA) ----------------
// grid (B*H, S/32), block 256 = 8 warps; each warp handles 4 queries.
__global__ __launch_bounds__(256) void attn_kernel(
    const float* __restrict__ Q, const float* __restrict__ K,
    const float* __restrict__ V, const unsigned char* __restrict__ mask,
    float* __restrict__ ctx)
{
    __shared__ float qs[32][68];
    __shared__ float kt[32][68];
    __shared__ float vt[32][68];
    __shared__ uint32_t qbits[32];
    __shared__ uint32_t needm_s;

    int bh = blockIdx.x;               // b*16 + h
    int b = bh >> 4, h = bh & 15;
    int qb = blockIdx.y;
    int s0 = qb * 32;
    int tid = threadIdx.x, warp = tid >> 5, lane = tid & 31;

    // load Q tile 32x64 (512 float4, 2 per thread)
    const float* Qb = Q + ((size_t)bh * Sq + s0) * HDq;
    #pragma unroll
    for (int i = 0; i < 2; i++) {
        int idx = tid + i * 256;
        int row = idx >> 4, col = (idx & 15) << 2;
        float4 f = *(const float4*)(Qb + row * HDq + col);
        qs[row][col] = f.x; qs[row][col+1] = f.y; qs[row][col+2] = f.z; qs[row][col+3] = f.w;
    }

    // mask bits per query + block union (warp 0)
    if (warp == 0) {
        const unsigned char* mrow = mask + ((size_t)b * Sq + s0 + lane) * Rq;
        uint32_t bits = 0;
        #pragma unroll
        for (int r = 0; r < Rq; r++) bits |= (mrow[r] ? 1u : 0u) << r;
        qbits[lane] = bits;
        #pragma unroll
        for (int o = 16; o; o >>= 1) bits |= __shfl_xor_sync(0xffffffffu, bits, o);
        if (lane == 0) needm_s = bits;
    }
    __syncthreads();
    uint32_t need = needm_s;
    uint32_t myb[4];
    #pragma unroll
    for (int j = 0; j < 4; j++) myb[j] = qbits[warp * 4 + j];

    float mr[4], l[4], c0[4], c1[4];
    #pragma unroll
    for (int j = 0; j < 4; j++) { mr[j] = -INFINITY; l[j] = 0.f; c0[j] = 0.f; c1[j] = 0.f; }

    const float* kbh = K + (size_t)bh * Sq * HDq;
    const float* vbh = V + (size_t)bh * Sq * HDq;

    for (int r = 0; r < 32; r++) {
        if (!((need >> r) & 1u)) continue;
        __syncthreads();   // protect kt/vt from previous iteration readers
        const float* kb = kbh + (size_t)r * 32 * HDq;
        const float* vb = vbh + (size_t)r * 32 * HDq;
        #pragma unroll
        for (int i = 0; i < 2; i++) {
            int idx = tid + i * 256;
            int row = idx >> 4, col = (idx & 15) << 2;
            float4 f = *(const float4*)(kb + row * HDq + col);
            kt[row][col] = f.x; kt[row][col+1] = f.y; kt[row][col+2] = f.z; kt[row][col+3] = f.w;
            float4 g = *(const float4*)(vb + row * HDq + col);
            vt[row][col] = g.x; vt[row][col+1] = g.y; vt[row][col+2] = g.z; vt[row][col+3] = g.w;
        }
        __syncthreads();

        #pragma unroll
        for (int j = 0; j < 4; j++) {
            if (!((myb[j] >> r) & 1u)) continue;
            int qi = warp * 4 + j;
            float sc = 0.f;
            #pragma unroll
            for (int d = 0; d < HDq; d += 4) {
                float4 kv = *(const float4*)&kt[lane][d];
                float4 qv = *(const float4*)&qs[qi][d];
                sc += kv.x * qv.x + kv.y * qv.y + kv.z * qv.z + kv.w * qv.w;
            }
            sc *= 0.125f;
            float bmax = warp_max(sc);
            float mnew = fmaxf(mr[j], bmax);
            float p = __expf(sc - mnew);
            float scale = __expf(mr[j] - mnew);
            l[j] = l[j] * scale + warp_sum(p);
            c0[j] *= scale; c1[j] *= scale;
            #pragma unroll 8
            for (int t = 0; t < 32; t++) {
                float pj = __shfl_sync(0xffffffffu, p, t);
                c0[j] += pj * vt[t][lane];
                c1[j] += pj * vt[t][lane + 32];
            }
            mr[j] = mnew;
        }
    }

    #pragma unroll
    for (int j = 0; j < 4; j++) {
        int s = s0 + warp * 4 + j;
        float inv = 1.0f / l[j];
        float* cp = ctx + ((size_t)(b * Sq + s)) * Dq + h * HDq;
        cp[lane] = rna_tf32(c0[j] * inv);
        cp[lane + 32] = rna_tf32(c1[j] * inv);
    }
}

// ---------------- host launch ----------------
extern "C" void kernel_launch(void* const* d_in, const int* in_sizes, int n_in,
                              void* d_out, int out_size) {
    const float* x      = (const float*)d_in[0];
    const float* Wu     = (const float*)d_in[1];
    const float* Wk_sel = (const float*)d_in[2];
    const float* Wq_sel = (const float*)d_in[3];
    const float* Wq     = (const float*)d_in[4];
    const float* Wk     = (const float*)d_in[5];
    const float* Wv     = (const float*)d_in[6];
    const float* Wo     = (const float*)d_in[7];
    float* out = (float*)d_out;

    float *xr, *WuT, *WoT, *WkselT, *Wcat;
    float *pooled, *root, *ksel, *qsel, *q, *k, *v, *ctx;
    unsigned char* mask;
    cudaGetSymbolAddress((void**)&xr,     g_xr);
    cudaGetSymbolAddress((void**)&WuT,    g_WuT);
    cudaGetSymbolAddress((void**)&WoT,    g_WoT);
    cudaGetSymbolAddress((void**)&WkselT, g_WkselT);
    cudaGetSymbolAddress((void**)&Wcat,   g_Wcat);
    cudaGetSymbolAddress((void**)&pooled, g_pooled);
    cudaGetSymbolAddress((void**)&root,   g_root);
    cudaGetSymbolAddress((void**)&ksel,   g_ksel);
    cudaGetSymbolAddress((void**)&qsel,   g_qsel);
    cudaGetSymbolAddress((void**)&mask,   g_mask);
    cudaGetSymbolAddress((void**)&q,      g_q);
    cudaGetSymbolAddress((void**)&k,      g_k);
    cudaGetSymbolAddress((void**)&v,      g_v);
    cudaGetSymbolAddress((void**)&ctx,    g_ctx);

    cudaFuncSetAttribute(mma_gemm, cudaFuncAttributeMaxDynamicSharedMemorySize, SM_GEMM_BYTES);

    // Launch order arranged so the FUSED GEMM is the 6th launch (ncu -s 5 -c 1).
    // (1) round x
    round_copy_kernel<<<(Mtok * Dq / 4 + 255) / 256, 256>>>((const float4*)x, (float4*)xr, Mtok * Dq / 4);
    // (2-5) Wcat transposes
    transpose_round_kernel<<<dim3(DAq / 32, Dq / 32), dim3(32, 8)>>>(Wq_sel, Wcat, Dq, DAq);
    transpose_round_kernel<<<dim3(Dq / 32, Dq / 32), dim3(32, 8)>>>(Wq, Wcat + (size_t)DAq * Dq, Dq, Dq);
    transpose_round_kernel<<<dim3(Dq / 32, Dq / 32), dim3(32, 8)>>>(Wk, Wcat + (size_t)(DAq + Dq) * Dq, Dq, Dq);
    transpose_round_kernel<<<dim3(Dq / 32, Dq / 32), dim3(32, 8)>>>(Wv, Wcat + (size_t)(DAq + 2 * Dq) * Dq, Dq, Dq);
    // (6) fused: [qsel | q | k | v] = xr @ Wcat^T   <-- profiled launch
    mma_gemm<<<dim3(NCAT / GBN, Mtok / GBM), 256, SM_GEMM_BYTES>>>(
        xr, Wcat, qsel, Mtok, NCAT, Dq, 4, nullptr, q, k, v);
    // (7-9) remaining transposes
    transpose_round_kernel<<<dim3(Dq / 32, Dq / 32), dim3(32, 8)>>>(Wu, WuT, Dq, Dq);
    transpose_round_kernel<<<dim3(Dq / 32, Dq / 32), dim3(32, 8)>>>(Wo, WoT, Dq, Dq);
    transpose_round_kernel<<<dim3(DAq / 32, Dq / 32), dim3(32, 8)>>>(Wk_sel, WkselT, Dq, DAq);
    // (10) pooling
    pool_kernel<<<Bq * Rq, 256>>>(x, pooled);
    // (11) root = pooled @ Wu
    mma_gemm<<<dim3(Dq / GBN, (Bq * Rq) / GBM), 256, SM_GEMM_BYTES>>>(
        pooled, WuT, root, Bq * Rq, Dq, Dq, 3, nullptr, nullptr, nullptr, nullptr);
    // (12) ksel = root @ Wk_sel
    mma_gemm<<<dim3(DAq / GBN, (Bq * Rq) / GBM), 256, SM_GEMM_BYTES>>>(
        root, WkselT, ksel, Bq * Rq, DAq, Dq, 0, nullptr, nullptr, nullptr, nullptr);
    // (13) selection mask
    select_kernel<<<dim3(Bq, Sq / 8), 256>>>(qsel, ksel, mask);
    // (14) attention (32 queries per CTA)
    attn_kernel<<<dim3(Bq * Hq, Sq / 32), 256>>>(q, k, v, mask, ctx);
    // (15) out = ctx @ Wo + x
    mma_gemm<<<dim3(Dq / GBN, Mtok / GBM), 256, SM_GEMM_BYTES>>>(
        ctx, WoT, out, Mtok, Dq, Dq, 2, x, nullptr, nullptr, nullptr);
}